// round 17
// baseline (speedup 1.0000x reference)
#include <cuda_runtime.h>
#include <cuda_bf16.h>
#include <cstdint>

#define NCLS 64
#define DIM 256
#define NROWS 65536
#define TOTROWS 131072

__device__ __align__(16) __nv_bfloat162 g_scratch_bf[2 * 256 * NCLS * 128]; // 16MB
__device__ __align__(16) float g_wpart[4096 * 16 * 8];   // 2MB partials, elem-major
__device__ int    g_icnt[2][NCLS];
__device__ __align__(16) __nv_bfloat16 g_wbf[4 * 8192];  // W bf16 swizzled, cols interleaved
__device__ float  g_inv[3 * NCLS];
__device__ double g_acc;
__device__ int    g_lstride;

__device__ __forceinline__ uint32_t smem_u32(const void* p) {
    uint32_t r;
    asm("{ .reg .u64 t; cvta.to.shared.u64 t, %1; cvt.u32.u64 %0, t; }" : "=r"(r) : "l"(p));
    return r;
}
__device__ __forceinline__ void cpa16(uint32_t dst, const void* src) {
    asm volatile("cp.async.cg.shared.global [%0], [%1], 16;" :: "r"(dst), "l"(src));
}
__device__ __forceinline__ void cp_commit() { asm volatile("cp.async.commit_group;"); }
template<int N> __device__ __forceinline__ void cp_wait() {
    asm volatile("cp.async.wait_group %0;" :: "n"(N));
}
__device__ __forceinline__ uint32_t lds_u32(uint32_t a) {
    uint32_t v; asm volatile("ld.shared.b32 %0, [%1];" : "=r"(v) : "r"(a)); return v;
}
__device__ __forceinline__ void mma_bf16(float* d, const uint32_t* a, const uint32_t* b) {
    asm volatile("mma.sync.aligned.m16n8k16.row.col.f32.bf16.bf16.f32 "
        "{%0,%1,%2,%3}, {%4,%5,%6,%7}, {%8,%9}, {%0,%1,%2,%3};"
        : "+f"(d[0]), "+f"(d[1]), "+f"(d[2]), "+f"(d[3])
        : "r"(a[0]), "r"(a[1]), "r"(a[2]), "r"(a[3]), "r"(b[0]), "r"(b[1]));
}
__device__ __forceinline__ float qsum(float v) {
    v += __shfl_xor_sync(~0u, v, 1);
    v += __shfl_xor_sync(~0u, v, 2);
    return v;
}
__device__ __forceinline__ float ex2(float x) {
    float y; asm("ex2.approx.ftz.f32 %0, %1;" : "=f"(y) : "f"(x)); return y;
}
// pack two f32 into bf16x2 (rn), returning the raw 32-bit word
__device__ __forceinline__ uint32_t pack_bf16x2(float lo, float hi) {
    uint32_t r;
    asm("cvt.rn.bf16x2.f32 %0, %1, %2;" : "=r"(r) : "f"(hi), "f"(lo));
    return r;
}

// ---- zero + label-dtype detect ----
__global__ void k_zero(const int* __restrict__ lbl) {
    int i = threadIdx.x;
    if (i < 128) ((int*)g_icnt)[i] = 0;
    if (i == 128) g_acc = 0.0;
    if (i == 129) {
        bool oz = true;
        #pragma unroll
        for (int j = 0; j < 64; ++j) oz &= (lbl[2 * j + 1] == 0);
        g_lstride = oz ? 2 : 1;
    }
}

// ---- segment sums: per-warp rings; NO feat copy anymore ----
__global__ void __launch_bounds__(128) k_segsum(const float* __restrict__ src,
        const float* __restrict__ trg, const int* __restrict__ sl,
        const int* __restrict__ tl) {
    extern __shared__ float smf[];
    float2* bins = (float2*)(smf + 4 * 5 * 512);
    __shared__ int lbl_s[256];
    const int feat = blockIdx.x >> 8, chunk = blockIdx.x & 255;
    const float* fp = feat ? trg : src;
    const int*   lp = feat ? tl : sl;
    const int ls = g_lstride, tid = threadIdx.x;
    const int lane = tid & 31, w = tid >> 5;
    const int base = chunk * 256;
    const uint32_t ringb = smem_u32(smf) + w * 10240;
    const float* fin = fp + (size_t)base * DIM + w * 64;

    #pragma unroll
    for (int s = 0; s < 4; ++s) {
        #pragma unroll
        for (int j = 0; j < 4; ++j) {
            int uu = j * 32 + lane;
            int row = uu >> 4, c16 = uu & 15;
            cpa16(ringb + (uint32_t)(s * 2048 + uu * 16),
                  fin + (size_t)(s * 8 + row) * DIM + c16 * 4);
        }
        cp_commit();
    }

    lbl_s[tid]       = lp[(base + tid) * ls] & 63;
    lbl_s[tid + 128] = lp[(base + tid + 128) * ls] & 63;
    #pragma unroll
    for (int c = 0; c < NCLS; ++c) bins[c * 128 + tid] = make_float2(0.f, 0.f);
    __syncthreads();

    int ws = 4, ps = 0;
    for (int s = 0; s < 32; ++s) {
        if (s + 4 < 32) {
            #pragma unroll
            for (int j = 0; j < 4; ++j) {
                int uu = j * 32 + lane;
                int row = uu >> 4, c16 = uu & 15;
                cpa16(ringb + (uint32_t)(ws * 2048 + uu * 16),
                      fin + (size_t)((s + 4) * 8 + row) * DIM + c16 * 4);
            }
        }
        cp_commit();
        cp_wait<4>();

        const float2* sp = (const float2*)(smf + (w * 5 + ps) * 512);
        #pragma unroll
        for (int i = 0; i < 8; ++i) {
            int r = s * 8 + i;
            float2 v = sp[i * 32 + lane];
            int c = lbl_s[r];
            float2 b = bins[c * 128 + tid];
            b.x += v.x; b.y += v.y;
            bins[c * 128 + tid] = b;
        }
        if (++ws == 5) ws = 0;
        if (++ps == 5) ps = 0;
    }

    if (tid < NCLS) {
        int cnt = 0;
        #pragma unroll 8
        for (int r = 0; r < 256; ++r) cnt += (lbl_s[r] == tid);
        atomicAdd(&g_icnt[feat][tid], cnt);
    }

    __nv_bfloat162* sc = g_scratch_bf + ((size_t)(feat * 256 + chunk) * NCLS) * 128 + tid;
    #pragma unroll 8
    for (int c = 0; c < NCLS; ++c)
        sc[c * 128] = __float22bfloat162_rn(bins[c * 128 + tid]);
}

// ---- reduce stage 1 (unchanged) ----
__global__ void __launch_bounds__(256) k_red() {
    int q = blockIdx.x * 256 + threadIdx.x;
    int p = q >> 12;
    int rem = q & 4095;
    int cls = rem >> 5, quad = rem & 31;
    int feat = cls >> 6, c = cls & 63;
    const uint4* srcp = (const uint4*)(g_scratch_bf
        + ((size_t)((feat * 256 + p * 16) * NCLS + c)) * 128 + quad * 4);
    float s[8] = {0.f, 0.f, 0.f, 0.f, 0.f, 0.f, 0.f, 0.f};
    #pragma unroll 16
    for (int ch = 0; ch < 16; ++ch) {
        uint4 v = srcp[(size_t)ch * 2048];
        const __nv_bfloat162* pv = (const __nv_bfloat162*)&v;
        #pragma unroll
        for (int t2 = 0; t2 < 4; ++t2) {
            float2 f = __bfloat1622float2(pv[t2]);
            s[2 * t2] += f.x; s[2 * t2 + 1] += f.y;
        }
    }
    float4* d = (float4*)(g_wpart + (size_t)rem * 128 + p * 8);
    d[0] = make_float4(s[0], s[1], s[2], s[3]);
    d[1] = make_float4(s[4], s[5], s[6], s[7]);
}

// ---- reduce stage 2 (bf16 W, interleaved cols, shfl combine) ----
__global__ void __launch_bounds__(256) k_prep() {
    int u = blockIdx.x * 256 + threadIdx.x;    // 0..32767
    int ef = u >> 3, s = u & 7;
    int jq = s & 1, psub = s >> 1;
    const float4* row = (const float4*)(g_wpart + (size_t)ef * 128);
    float4 a = make_float4(0.f, 0.f, 0.f, 0.f);
    #pragma unroll
    for (int i = 0; i < 4; ++i) {
        float4 v = row[psub * 2 + jq + i * 8];
        a.x += v.x; a.y += v.y; a.z += v.z; a.w += v.w;
    }
    a.x += __shfl_xor_sync(~0u, a.x, 2); a.y += __shfl_xor_sync(~0u, a.y, 2);
    a.z += __shfl_xor_sync(~0u, a.z, 2); a.w += __shfl_xor_sync(~0u, a.w, 2);
    a.x += __shfl_xor_sync(~0u, a.x, 4); a.y += __shfl_xor_sync(~0u, a.y, 4);
    a.z += __shfl_xor_sync(~0u, a.z, 4); a.w += __shfl_xor_sync(~0u, a.w, 4);
    if (psub == 0) {
        int cls = ef >> 5, quad = ef & 31;
        int nc = ((cls & 63) << 1) | (cls >> 6);
        int k0 = quad * 8;
        int kc = k0 >> 6, uu = (k0 >> 3) & 7;
        __nv_bfloat162* d2 = (__nv_bfloat162*)(g_wbf + kc * 8192
                            + (nc * 8 + (uu ^ (nc & 7))) * 8 + jq * 4);
        d2[0] = __floats2bfloat162_rn(a.x, a.y);
        d2[1] = __floats2bfloat162_rn(a.z, a.w);
    }
    if (u < 3 * NCLS) {
        int which = u >> 6, c2 = u & 63;
        float cs = (float)g_icnt[0][c2], ct = (float)g_icnt[1][c2];
        g_inv[u] = (which == 0) ? 1.f / cs : (which == 1) ? 1.f / ct : 1.f / (cs + ct);
    }
}

// ---- persistent GEMM + KL; reads f32 feats, converts in-kernel ----
#define WB_OFF  0
#define BF_OFF  65536
#define F32_OFF 81920
#define PM_OFF  147456
#define INV_OFF 159744
#define RED_OFF 160512
#define SMEM_MAIN 160544

__global__ void __launch_bounds__(256) k_main(const float* __restrict__ src,
                                              const float* __restrict__ trg) {
    extern __shared__ unsigned char sm[];
    float* pm    = (float*)(sm + PM_OFF);
    float* inv_s = (float*)(sm + INV_OFF);
    float* red   = (float*)(sm + RED_OFF);
    const uint32_t sb = smem_u32(sm);
    const float* f32buf = (const float*)(sm + F32_OFF);
    const int tid = threadIdx.x, w = tid >> 5, lane = tid & 31;
    const int g = lane >> 2, t = lane & 3;
    const int wm = w >> 2, wn = w & 3;
    const int b = blockIdx.x;
    const int nt = (b < 136) ? 4 : 3;           // 136*4 + 160*3 = 1024 tiles
    const int totc = nt * 4;

    if (tid < 192) inv_s[tid] = g_inv[tid];

    // W once (bf16 chunk images)
    #pragma unroll
    for (int j = 0; j < 16; ++j) {
        int uu = j * 256 + tid;
        cpa16(sb + WB_OFF + uu * 16, g_wbf + uu * 8);
    }
    cp_commit();
    {   // first f32 chunk: 32KB = 2048 units; thread owns units j*256+tid
        const float* fr = (b < 512) ? src + (size_t)b * 128 * DIM
                                    : trg + (size_t)(b - 512) * 128 * DIM;
        #pragma unroll
        for (int j = 0; j < 8; ++j) {
            int uu = j * 256 + tid, row = uu >> 4, c16 = uu & 15;
            cpa16(sb + F32_OFF + uu * 16, fr + (size_t)row * DIM + c16 * 4);
        }
        cp_commit();
    }

    const float LOG2E = 1.44269504f;
    float invS[4], invT[4], invM[4];
    float acc[4][4][4];
    float Jacc = 0.f;

    #pragma unroll
    for (int x = 0; x < 4; ++x)
        #pragma unroll
        for (int y = 0; y < 4; ++y)
            #pragma unroll
            for (int z = 0; z < 4; ++z) acc[x][y][z] = 0.f;

    for (int c = 0; c < totc; ++c) {
        // prefetch next f32 chunk (thread-owned units: no cross-thread hazard)
        if (c + 1 < totc) {
            int tg = b + ((c + 1) >> 2) * 296, kc = (c + 1) & 3;
            const float* fr = (tg < 512) ? src + (size_t)tg * 128 * DIM
                                         : trg + (size_t)(tg - 512) * 128 * DIM;
            uint32_t slot = sb + F32_OFF + ((c + 1) & 1) * 32768;
            #pragma unroll
            for (int j = 0; j < 8; ++j) {
                int uu = j * 256 + tid, row = uu >> 4, c16 = uu & 15;
                cpa16(slot + uu * 16, fr + (size_t)row * DIM + kc * 64 + c16 * 4);
            }
            cp_commit();
            cp_wait<1>();
        } else {
            cp_commit();
            cp_wait<0>();
        }

        // convert own units f32 -> bf16 swizzled image (thread-local, no barrier yet)
        {
            const float* fsrc = f32buf + (c & 1) * 8192;
            #pragma unroll
            for (int j = 0; j < 8; ++j) {
                int uu = j * 256 + tid, row = uu >> 4, c16 = uu & 15;
                float4 v = *(const float4*)(fsrc + uu * 4);
                uint32_t lo = pack_bf16x2(v.x, v.y);
                uint32_t hi = pack_bf16x2(v.z, v.w);
                int u8 = c16 >> 1, low = (c16 & 1) * 8;
                uint32_t dst = sb + BF_OFF
                    + (uint32_t)(row * 8 + (u8 ^ (row & 7))) * 16 + low;
                asm volatile("st.shared.v2.b32 [%0], {%1, %2};"
                             :: "r"(dst), "r"(lo), "r"(hi));
            }
        }
        __syncthreads();    // bf16 image visible to all warps

        const uint32_t fb = sb + BF_OFF;
        const uint32_t wb = sb + WB_OFF + (c & 3) * 16384;
        #pragma unroll
        for (int s = 0; s < 4; ++s) {
            uint32_t a[4][4], bb[4][2];
            #pragma unroll
            for (int mt = 0; mt < 4; ++mt) {
                int r0 = wm * 64 + mt * 16 + g, r1 = r0 + 8;
                a[mt][0] = lds_u32(fb + (uint32_t)(r0 * 8 + ((2*s)   ^ (r0 & 7))) * 16 + 4 * t);
                a[mt][1] = lds_u32(fb + (uint32_t)(r1 * 8 + ((2*s)   ^ (r1 & 7))) * 16 + 4 * t);
                a[mt][2] = lds_u32(fb + (uint32_t)(r0 * 8 + ((2*s+1) ^ (r0 & 7))) * 16 + 4 * t);
                a[mt][3] = lds_u32(fb + (uint32_t)(r1 * 8 + ((2*s+1) ^ (r1 & 7))) * 16 + 4 * t);
            }
            #pragma unroll
            for (int ntv = 0; ntv < 4; ++ntv) {
                int cn = wn * 32 + ntv * 8 + g;
                bb[ntv][0] = lds_u32(wb + (uint32_t)(cn * 8 + ((2*s)   ^ (cn & 7))) * 16 + 4 * t);
                bb[ntv][1] = lds_u32(wb + (uint32_t)(cn * 8 + ((2*s+1) ^ (cn & 7))) * 16 + 4 * t);
            }
            #pragma unroll
            for (int mt = 0; mt < 4; ++mt)
                #pragma unroll
                for (int ntv = 0; ntv < 4; ++ntv)
                    mma_bf16(acc[mt][ntv], a[mt], bb[ntv]);
        }
        __syncthreads();    // all fragment reads done before next convert

        if ((c & 3) == 3) {
            #pragma unroll
            for (int ntv = 0; ntv < 4; ++ntv) {
                int cc = wn * 16 + ntv * 4 + t;
                invS[ntv] = inv_s[cc] * LOG2E;
                invT[ntv] = inv_s[64 + cc] * LOG2E;
                invM[ntv] = inv_s[128 + cc] * LOG2E;
            }
            #pragma unroll
            for (int mt = 0; mt < 4; ++mt) {
                #pragma unroll
                for (int h = 0; h < 2; ++h) {
                    float Z0 = 0.f, Z1 = 0.f, Z2 = 0.f;
                    float B0 = 0.f, B1 = 0.f, B2 = 0.f;
                    #pragma unroll
                    for (int ntv = 0; ntv < 4; ++ntv) {
                        float Sr = acc[mt][ntv][2*h], Tr = acc[mt][ntv][2*h+1];
                        float ps2 = Sr * invS[ntv], pt = Tr * invT[ntv],
                              pv = (Sr + Tr) * invM[ntv];
                        float eS = ex2(ps2), eT = ex2(pt), eM = ex2(pv);
                        float dw = ps2 - pt, dx = ps2 - pv, dy = pt - pv;
                        Z0 += eS; Z1 += eT; Z2 += eM;
                        B0 += eS * (dw + dx);
                        B1 += eT * (dy - dw);
                        B2 -= eM * (dx + dy);
                    }
                    Z0 = qsum(Z0); Z1 = qsum(Z1); Z2 = qsum(Z2);
                    B0 = qsum(B0); B1 = qsum(B1); B2 = qsum(B2);
                    if (t == 0) {
                        int row = wm * 64 + mt * 16 + g + 8 * h;
                        float* d = pm + (row * 4 + wn) * 6;
                        d[0] = Z0; d[1] = Z1; d[2] = Z2;
                        d[3] = B0; d[4] = B1; d[5] = B2;
                    }
                }
            }
            __syncthreads();
            if (tid < 128) {
                float v[6];
                #pragma unroll
                for (int i = 0; i < 6; ++i)
                    v[i] = pm[(tid * 4 + 0) * 6 + i] + pm[(tid * 4 + 1) * 6 + i]
                         + pm[(tid * 4 + 2) * 6 + i] + pm[(tid * 4 + 3) * 6 + i];
                Jacc += (__fdividef(v[3], v[0]) + __fdividef(v[4], v[1])
                       + __fdividef(v[5], v[2])) * 0.69314718f;
            }
            #pragma unroll
            for (int x = 0; x < 4; ++x)
                #pragma unroll
                for (int y = 0; y < 4; ++y)
                    #pragma unroll
                    for (int z = 0; z < 4; ++z) acc[x][y][z] = 0.f;
            __syncthreads();
        }
    }

    #pragma unroll
    for (int o = 16; o; o >>= 1) Jacc += __shfl_xor_sync(~0u, Jacc, o);
    if (lane == 0) red[w] = Jacc;
    __syncthreads();
    if (tid == 0) {
        float bs = 0.f;
        #pragma unroll
        for (int i = 0; i < 8; ++i) bs += red[i];
        atomicAdd(&g_acc, (double)bs);
    }
}

__global__ void k_final(float* out) {
    out[0] = (float)(g_acc * (0.5 / (3.0 * 131072.0 * 64.0)));
}

extern "C" void kernel_launch(void* const* d_in, const int* in_sizes, int n_in,
                              void* d_out, int out_size) {
    const float* src = (const float*)d_in[0];
    const float* trg = (const float*)d_in[1];
    const int*   sl  = (const int*)d_in[2];
    const int*   tl  = (const int*)d_in[3];

    cudaFuncSetAttribute(k_segsum, cudaFuncAttributeMaxDynamicSharedMemorySize, 106496);
    cudaFuncSetAttribute(k_main,   cudaFuncAttributeMaxDynamicSharedMemorySize, SMEM_MAIN);

    k_zero<<<1, 256>>>(sl);
    k_segsum<<<512, 128, 106496>>>(src, trg, sl, tl);
    k_red<<<256, 256>>>();
    k_prep<<<128, 256>>>();
    k_main<<<296, 256, SMEM_MAIN>>>(src, trg);
    k_final<<<1, 1>>>((float*)d_out);
}